// round 1
// baseline (speedup 1.0000x reference)
#include <cuda_runtime.h>
#include <cuda_bf16.h>

// GPT2 attention block: B=2, S=2048, D=768, H=12, hd=64
// Phase 1: QKV GEMM [4096,768]@[768,2304] + bias -> split heads into g_q/g_k/g_v
// Phase 2: causal flash attention per (b,h,128-row q tile) -> g_att [B,S,D]
// Phase 3: proj GEMM [4096,768]@[768,768] + bias -> d_out

#define B_ 2
#define S_ 2048
#define D_ 768
#define H_ 12
#define HD_ 64
#define M_ (B_ * S_)        // 4096
#define N_QKV (3 * D_)      // 2304
#define MASKED_BIAS (-10000.0f)

// Scratch (no cudaMalloc allowed)
__device__ float g_q[B_ * H_ * S_ * HD_];
__device__ float g_k[B_ * H_ * S_ * HD_];
__device__ float g_v[B_ * H_ * S_ * HD_];
__device__ float g_att[M_ * D_];

// ---------------------------------------------------------------------------
// Classic SGEMM: 128x128 block tile, BK=8, 8x8 per thread, 256 threads.
// MODE 0: C = X @ Wqkv + bqkv, scattered into g_q/g_k/g_v head layout
// MODE 1: C = g_att @ Wproj + bproj, written row-major to out
// ---------------------------------------------------------------------------
template <int MODE>
__global__ __launch_bounds__(256) void sgemm_kernel(
    const float* __restrict__ A,   // [M, K] row-major
    const float* __restrict__ Bm,  // [K, N] row-major
    const float* __restrict__ bias,// [N]
    float* __restrict__ Cout,      // MODE 1 only
    int K, int N)
{
    constexpr int BM = 128, BN = 128, BK = 8;
    __shared__ float As[BK][BM];
    __shared__ float Bs[BK][BN];

    const int tid = threadIdx.x;
    const int bm = blockIdx.y;
    const int bn = blockIdx.x;
    const int tx = tid % 16;        // 16 cols of threads
    const int ty = tid / 16;        // 16 rows of threads

    // A load mapping: 128 rows x 8 cols; one float4 per thread
    const int arow = tid >> 1;            // 0..127
    const int acol = (tid & 1) * 4;       // 0 or 4
    // B load mapping: 8 rows x 128 cols; one float4 per thread
    const int brow = tid >> 5;            // 0..7
    const int bcol = (tid & 31) * 4;      // 0..124

    const float* Aptr = A + (size_t)(bm * BM + arow) * K + acol;
    const float* Bptr = Bm + (size_t)brow * N + bn * BN + bcol;

    float acc[8][8];
#pragma unroll
    for (int i = 0; i < 8; i++)
#pragma unroll
        for (int j = 0; j < 8; j++) acc[i][j] = 0.f;

    const int ksteps = K / BK;
    for (int kt = 0; kt < ksteps; kt++) {
        float4 a4 = *(const float4*)(Aptr + kt * BK);
        float4 b4 = *(const float4*)(Bptr + (size_t)kt * BK * N);
        __syncthreads();
        As[acol + 0][arow] = a4.x;
        As[acol + 1][arow] = a4.y;
        As[acol + 2][arow] = a4.z;
        As[acol + 3][arow] = a4.w;
        *(float4*)&Bs[brow][bcol] = b4;
        __syncthreads();
#pragma unroll
        for (int kk = 0; kk < BK; kk++) {
            float ra[8], rb[8];
            *(float4*)(ra)     = *(const float4*)&As[kk][ty * 8];
            *(float4*)(ra + 4) = *(const float4*)&As[kk][ty * 8 + 4];
            *(float4*)(rb)     = *(const float4*)&Bs[kk][tx * 8];
            *(float4*)(rb + 4) = *(const float4*)&Bs[kk][tx * 8 + 4];
#pragma unroll
            for (int i = 0; i < 8; i++)
#pragma unroll
                for (int j = 0; j < 8; j++)
                    acc[i][j] += ra[i] * rb[j];
        }
    }

#pragma unroll
    for (int i = 0; i < 8; i++) {
        const int m = bm * BM + ty * 8 + i;
#pragma unroll
        for (int j = 0; j < 8; j++) {
            const int n = bn * BN + tx * 8 + j;
            float val = acc[i][j] + bias[n];
            if (MODE == 0) {
                // scatter into q/k/v head layout [B,H,S,hd]
                const int which = n / D_;
                const int d2 = n - which * D_;
                const int h = d2 >> 6;
                const int hi = d2 & 63;
                const int b = m >> 11;       // /2048
                const int s = m & 2047;
                float* dst = (which == 0) ? g_q : (which == 1) ? g_k : g_v;
                dst[(((size_t)(b * H_ + h) * S_) + s) * HD_ + hi] = val;
            } else {
                Cout[(size_t)m * N + n] = val;
            }
        }
    }
}

// ---------------------------------------------------------------------------
// Flash attention: block = 128 threads = 128 query rows. Bc = 32 key cols.
// Each thread holds its q row (pre-scaled) and 64 fp32 output accumulators
// in registers; K/V tiles live in smem (reads are warp-broadcast).
// ---------------------------------------------------------------------------
__global__ __launch_bounds__(128) void attn_kernel()
{
    const int qtile = blockIdx.x;   // 0..15
    const int h = blockIdx.y;       // 0..11
    const int b = blockIdx.z;       // 0..1
    const int r = threadIdx.x;      // 0..127
    const int qi = qtile * 128 + r;

    const float* qbase = g_q + ((size_t)(b * H_ + h) * S_) * HD_;
    const float* kbase = g_k + ((size_t)(b * H_ + h) * S_) * HD_;
    const float* vbase = g_v + ((size_t)(b * H_ + h) * S_) * HD_;

    float qreg[HD_];
#pragma unroll
    for (int d4 = 0; d4 < HD_; d4 += 4) {
        float4 t = *(const float4*)&qbase[(size_t)qi * HD_ + d4];
        qreg[d4 + 0] = t.x * 0.125f;   // 1/sqrt(64)
        qreg[d4 + 1] = t.y * 0.125f;
        qreg[d4 + 2] = t.z * 0.125f;
        qreg[d4 + 3] = t.w * 0.125f;
    }

    float accd[HD_];
#pragma unroll
    for (int d = 0; d < HD_; d++) accd[d] = 0.f;
    float mrun = -1e30f;
    float lrun = 0.f;

    __shared__ float Ks[32][HD_];
    __shared__ float Vs[32][HD_];

    const int ntiles = (qtile + 1) * 4;   // keys up to (qtile+1)*128
    for (int t = 0; t < ntiles; t++) {
        __syncthreads();
        // cooperative load: 32x64 floats = 512 float4 per matrix, 4 per thread
        const float4* ksrc = (const float4*)(kbase + (size_t)t * 32 * HD_);
        const float4* vsrc = (const float4*)(vbase + (size_t)t * 32 * HD_);
        float4* kdst = (float4*)&Ks[0][0];
        float4* vdst = (float4*)&Vs[0][0];
#pragma unroll
        for (int u = 0; u < 4; u++) {
            kdst[u * 128 + r] = ksrc[u * 128 + r];
            vdst[u * 128 + r] = vsrc[u * 128 + r];
        }
        __syncthreads();

        // scores
        float s[32];
        const int kcol0 = t * 32;
#pragma unroll
        for (int c = 0; c < 32; c++) {
            float dot = 0.f;
#pragma unroll
            for (int d = 0; d < HD_; d++)
                dot += qreg[d] * Ks[c][d];
            s[c] = (kcol0 + c <= qi) ? dot : MASKED_BIAS;
        }

        // online softmax update
        float mt = mrun;
#pragma unroll
        for (int c = 0; c < 32; c++) mt = fmaxf(mt, s[c]);
        const float scale = expf(mrun - mt);
        float lsum = 0.f;
#pragma unroll
        for (int c = 0; c < 32; c++) {
            s[c] = expf(s[c] - mt);
            lsum += s[c];
        }
        lrun = lrun * scale + lsum;
        mrun = mt;
#pragma unroll
        for (int d = 0; d < HD_; d++) accd[d] *= scale;
#pragma unroll
        for (int c = 0; c < 32; c++) {
            const float pc = s[c];
#pragma unroll
            for (int d = 0; d < HD_; d++)
                accd[d] += pc * Vs[c][d];
        }
    }

    const float inv = 1.f / lrun;
    float* ob = g_att + ((size_t)(b * S_ + qi)) * D_ + h * HD_;
#pragma unroll
    for (int d4 = 0; d4 < HD_; d4 += 4) {
        float4 o;
        o.x = accd[d4 + 0] * inv;
        o.y = accd[d4 + 1] * inv;
        o.z = accd[d4 + 2] * inv;
        o.w = accd[d4 + 3] * inv;
        *(float4*)&ob[d4] = o;
    }
}

// ---------------------------------------------------------------------------
extern "C" void kernel_launch(void* const* d_in, const int* in_sizes, int n_in,
                              void* d_out, int out_size)
{
    const float* hidden  = (const float*)d_in[0];  // [2,2048,768]
    const float* c_attn_w = (const float*)d_in[1]; // [768,2304]
    const float* c_attn_b = (const float*)d_in[2]; // [2304]
    const float* c_proj_w = (const float*)d_in[3]; // [768,768]
    const float* c_proj_b = (const float*)d_in[4]; // [768]
    float* out = (float*)d_out;

    // Phase 1: QKV GEMM + head split
    {
        dim3 grid(N_QKV / 128, M_ / 128);   // (18, 32)
        sgemm_kernel<0><<<grid, 256>>>(hidden, c_attn_w, c_attn_b, nullptr,
                                       D_, N_QKV);
    }
    // Phase 2: causal flash attention
    {
        dim3 grid(S_ / 128, H_, B_);        // (16, 12, 2)
        attn_kernel<<<grid, 128>>>();
    }
    // Phase 3: output projection
    {
        float* g_att_ptr = nullptr;
        cudaGetSymbolAddress((void**)&g_att_ptr, g_att);
        dim3 grid(D_ / 128, M_ / 128);      // (6, 32)
        sgemm_kernel<1><<<grid, 256>>>(g_att_ptr, c_proj_w, c_proj_b, out,
                                       D_, D_);
    }
}

// round 2
// speedup vs baseline: 3.7494x; 3.7494x over previous
#include <cuda_runtime.h>
#include <cuda_bf16.h>
#include <cstdint>

// GPT2 attention block on tf32 tensor cores (mma.sync.m16n8k8)
// B=2, S=2048, D=768, H=12, hd=64

#define B_ 2
#define S_ 2048
#define D_ 768
#define H_ 12
#define HD_ 64
#define M_ (B_ * S_)        // 4096
#define N_QKV (3 * D_)      // 2304
#define MASKED_BIAS (-10000.0f)
#define L2E 1.4426950408889634f

// Scratch (no cudaMalloc allowed)
__device__ __align__(128) float g_q[B_ * H_ * S_ * HD_];
__device__ __align__(128) float g_k[B_ * H_ * S_ * HD_];
__device__ __align__(128) float g_v[B_ * H_ * S_ * HD_];
__device__ __align__(128) float g_att[M_ * D_];

// ---------------------------------------------------------------------------
// helpers
// ---------------------------------------------------------------------------
__device__ __forceinline__ uint32_t f2tf32(float x) {
    uint32_t r;
    asm("cvt.rna.tf32.f32 %0, %1;" : "=r"(r) : "f"(x));
    return r;
}

__device__ __forceinline__ float ex2(float x) {
    float y;
    asm("ex2.approx.f32 %0, %1;" : "=f"(y) : "f"(x));
    return y;
}

__device__ __forceinline__ void mma_tf32(float d[4], const uint32_t a[4],
                                         const uint32_t b[2], const float c[4]) {
    asm volatile(
        "mma.sync.aligned.m16n8k8.row.col.f32.tf32.tf32.f32 "
        "{%0,%1,%2,%3}, {%4,%5,%6,%7}, {%8,%9}, {%10,%11,%12,%13};\n"
        : "=f"(d[0]), "=f"(d[1]), "=f"(d[2]), "=f"(d[3])
        : "r"(a[0]), "r"(a[1]), "r"(a[2]), "r"(a[3]),
          "r"(b[0]), "r"(b[1]),
          "f"(c[0]), "f"(c[1]), "f"(c[2]), "f"(c[3]));
}

// ---------------------------------------------------------------------------
// TF32 GEMM: 128x128 block tile, BK=32, 256 threads (8 warps, 64x32 each).
// MODE 0: C = X @ Wqkv + bqkv -> scatter into g_q/g_k/g_v [B,H,S,hd]
// MODE 1: C = g_att @ Wproj + bproj -> Cout row-major
// ---------------------------------------------------------------------------
template <int MODE>
__global__ __launch_bounds__(256) void mma_gemm(
    const float* __restrict__ A,   // [M, K] row-major
    const float* __restrict__ Bm,  // [K, N] row-major
    const float* __restrict__ bias,
    float* __restrict__ Cout,
    int K, int N)
{
    constexpr int BM = 128, BN = 128, BK = 32;
    constexpr int AST = 36;    // As stride (floats): frag bank = lane -> conflict free
    constexpr int BST = 132;   // Bs stride

    __shared__ uint32_t As[BM * AST];
    __shared__ uint32_t Bs[BK * BST];

    const int tid = threadIdx.x;
    const int lane = tid & 31;
    const int wid = tid >> 5;
    const int wm = wid & 1;       // 0..1 (64-row halves)
    const int wn = wid >> 1;      // 0..3 (32-col strips)
    const int gid = lane >> 2;
    const int tig = lane & 3;
    const int bm = blockIdx.y, bn = blockIdx.x;

    const float* Abase = A + (size_t)(bm * BM) * K;
    const float* Bbase = Bm + bn * BN;

    float acc[4][4][4];
#pragma unroll
    for (int i = 0; i < 4; i++)
#pragma unroll
        for (int j = 0; j < 4; j++)
#pragma unroll
            for (int r = 0; r < 4; r++) acc[i][j][r] = 0.f;

    float4 pa[4], pb[4];

    // ---- load / store helpers (manually inlined pattern) ----
#define LOAD_A(kt)                                                            \
    {                                                                         \
        _Pragma("unroll")                                                     \
        for (int u = 0; u < 4; u++) {                                         \
            int idx = tid + u * 256;                                          \
            int row = idx >> 3, c4 = idx & 7;                                 \
            pa[u] = *(const float4*)(Abase + (size_t)row * K + (kt) * BK + c4 * 4); \
        }                                                                     \
    }
#define LOAD_B(kt)                                                            \
    {                                                                         \
        _Pragma("unroll")                                                     \
        for (int u = 0; u < 4; u++) {                                         \
            int idx = tid + u * 256;                                          \
            int row = idx >> 5, c4 = idx & 31;                                \
            pb[u] = *(const float4*)(Bbase + (size_t)((kt) * BK + row) * N + c4 * 4); \
        }                                                                     \
    }
#define STORE_AB()                                                            \
    {                                                                         \
        _Pragma("unroll")                                                     \
        for (int u = 0; u < 4; u++) {                                         \
            int idx = tid + u * 256;                                          \
            int row = idx >> 3, c4 = idx & 7;                                 \
            uint4 t;                                                          \
            t.x = f2tf32(pa[u].x); t.y = f2tf32(pa[u].y);                     \
            t.z = f2tf32(pa[u].z); t.w = f2tf32(pa[u].w);                     \
            *(uint4*)&As[row * AST + c4 * 4] = t;                             \
        }                                                                     \
        _Pragma("unroll")                                                     \
        for (int u = 0; u < 4; u++) {                                         \
            int idx = tid + u * 256;                                          \
            int row = idx >> 5, c4 = idx & 31;                                \
            uint4 t;                                                          \
            t.x = f2tf32(pb[u].x); t.y = f2tf32(pb[u].y);                     \
            t.z = f2tf32(pb[u].z); t.w = f2tf32(pb[u].w);                     \
            *(uint4*)&Bs[row * BST + c4 * 4] = t;                             \
        }                                                                     \
    }

    LOAD_A(0); LOAD_B(0);
    STORE_AB();
    __syncthreads();

    const int ksteps = K / BK;
    for (int kt = 0; kt < ksteps; kt++) {
        if (kt + 1 < ksteps) { LOAD_A(kt + 1); LOAD_B(kt + 1); }

#pragma unroll
        for (int kk = 0; kk < 4; kk++) {
            uint32_t af[4][4];
#pragma unroll
            for (int mt = 0; mt < 4; mt++) {
                int r0 = wm * 64 + mt * 16 + gid;
                int c = kk * 8 + tig;
                af[mt][0] = As[r0 * AST + c];
                af[mt][1] = As[(r0 + 8) * AST + c];
                af[mt][2] = As[r0 * AST + c + 4];
                af[mt][3] = As[(r0 + 8) * AST + c + 4];
            }
            uint32_t bf[4][2];
#pragma unroll
            for (int nt = 0; nt < 4; nt++) {
                int c0 = wn * 32 + nt * 8 + gid;
                bf[nt][0] = Bs[(kk * 8 + tig) * BST + c0];
                bf[nt][1] = Bs[(kk * 8 + tig + 4) * BST + c0];
            }
#pragma unroll
            for (int mt = 0; mt < 4; mt++)
#pragma unroll
                for (int nt = 0; nt < 4; nt++)
                    mma_tf32(acc[mt][nt], af[mt], bf[nt], acc[mt][nt]);
        }

        if (kt + 1 < ksteps) {
            __syncthreads();
            STORE_AB();
            __syncthreads();
        }
    }

    // epilogue
#pragma unroll
    for (int mt = 0; mt < 4; mt++) {
#pragma unroll
        for (int nt = 0; nt < 4; nt++) {
#pragma unroll
            for (int r = 0; r < 4; r++) {
                int m = bm * BM + wm * 64 + mt * 16 + gid + ((r >= 2) ? 8 : 0);
                int n = bn * BN + wn * 32 + nt * 8 + 2 * tig + (r & 1);
                float val = acc[mt][nt][r] + bias[n];
                if (MODE == 0) {
                    const int which = n / D_;
                    const int d2 = n - which * D_;
                    const int h = d2 >> 6;
                    const int hi = d2 & 63;
                    const int b = m >> 11;
                    const int s = m & 2047;
                    float* dst = (which == 0) ? g_q : (which == 1) ? g_k : g_v;
                    dst[(((size_t)(b * H_ + h) * S_) + s) * HD_ + hi] = val;
                } else {
                    Cout[(size_t)m * N + n] = val;
                }
            }
        }
    }
#undef LOAD_A
#undef LOAD_B
#undef STORE_AB
}

// ---------------------------------------------------------------------------
// Flash attention with tf32 mma. Block: 128 threads (4 warps), Br=64, Bc=64.
// Warp w owns 16 q rows. QK^T and P@V via m16n8k8. Online softmax in regs.
// ---------------------------------------------------------------------------
__global__ __launch_bounds__(128) void attn_mma()
{
    const int qtile = gridDim.x - 1 - blockIdx.x;  // heavy tiles launch first
    const int h = blockIdx.y;
    const int b = blockIdx.z;
    const int tid = threadIdx.x;
    const int lane = tid & 31;
    const int wid = tid >> 5;      // 0..3
    const int gid = lane >> 2;
    const int tig = lane & 3;

    const int q0 = qtile * 64;
    const int wrow0 = q0 + wid * 16;   // warp's first global q row

    const float* qb = g_q + ((size_t)(b * H_ + h) * S_) * HD_;
    const float* kb = g_k + ((size_t)(b * H_ + h) * S_) * HD_;
    const float* vb = g_v + ((size_t)(b * H_ + h) * S_) * HD_;

    // preload Q fragments (scaled by 1/sqrt(64), tf32)
    uint32_t qf[8][4];
#pragma unroll
    for (int kk = 0; kk < 8; kk++) {
        int r0 = wrow0 + gid;
        int c = kk * 8 + tig;
        qf[kk][0] = f2tf32(qb[(size_t)r0 * HD_ + c] * 0.125f);
        qf[kk][1] = f2tf32(qb[(size_t)(r0 + 8) * HD_ + c] * 0.125f);
        qf[kk][2] = f2tf32(qb[(size_t)r0 * HD_ + c + 4] * 0.125f);
        qf[kk][3] = f2tf32(qb[(size_t)(r0 + 8) * HD_ + c + 4] * 0.125f);
    }

    float o[8][4];
#pragma unroll
    for (int nt = 0; nt < 8; nt++)
#pragma unroll
        for (int r = 0; r < 4; r++) o[nt][r] = 0.f;

    float m0 = -1e30f, m1 = -1e30f, l0 = 0.f, l1 = 0.f;

    constexpr int KST = 72;   // smem stride -> conflict-free frag reads
    __shared__ uint32_t Ks[64 * KST];
    __shared__ uint32_t Vs[64 * KST];

    for (int t = 0; t <= qtile; t++) {
        const int k0 = t * 64;
        __syncthreads();
        // cooperative load K,V tile 64x64 (cvt to tf32)
#pragma unroll
        for (int u = 0; u < 8; u++) {
            int idx = tid + u * 128;
            int row = idx >> 4, c4 = idx & 15;
            float4 kv = *(const float4*)(kb + (size_t)(k0 + row) * HD_ + c4 * 4);
            uint4 tk;
            tk.x = f2tf32(kv.x); tk.y = f2tf32(kv.y);
            tk.z = f2tf32(kv.z); tk.w = f2tf32(kv.w);
            *(uint4*)&Ks[row * KST + c4 * 4] = tk;
            float4 vv = *(const float4*)(vb + (size_t)(k0 + row) * HD_ + c4 * 4);
            uint4 tv;
            tv.x = f2tf32(vv.x); tv.y = f2tf32(vv.y);
            tv.z = f2tf32(vv.z); tv.w = f2tf32(vv.w);
            *(uint4*)&Vs[row * KST + c4 * 4] = tv;
        }
        __syncthreads();

        const bool active = (k0 <= wrow0 + 15);
        if (active) {
            // ---- S = Q @ K^T ----
            float sfr[8][4];
#pragma unroll
            for (int nt = 0; nt < 8; nt++) {
#pragma unroll
                for (int r = 0; r < 4; r++) sfr[nt][r] = 0.f;
#pragma unroll
                for (int kk = 0; kk < 8; kk++) {
                    uint32_t bf[2];
                    bf[0] = Ks[(nt * 8 + gid) * KST + kk * 8 + tig];
                    bf[1] = Ks[(nt * 8 + gid) * KST + kk * 8 + tig + 4];
                    mma_tf32(sfr[nt], qf[kk], bf, sfr[nt]);
                }
            }

            const int r0 = wrow0 + gid;
            const int r1 = r0 + 8;
            const bool needmask = (k0 + 63 > wrow0);
            if (needmask) {
#pragma unroll
                for (int nt = 0; nt < 8; nt++) {
                    int c = k0 + nt * 8 + 2 * tig;
                    if (c > r0) sfr[nt][0] = MASKED_BIAS;
                    if (c + 1 > r0) sfr[nt][1] = MASKED_BIAS;
                    if (c > r1) sfr[nt][2] = MASKED_BIAS;
                    if (c + 1 > r1) sfr[nt][3] = MASKED_BIAS;
                }
            }

            // ---- online softmax ----
            float mx0 = -1e30f, mx1 = -1e30f;
#pragma unroll
            for (int nt = 0; nt < 8; nt++) {
                mx0 = fmaxf(mx0, fmaxf(sfr[nt][0], sfr[nt][1]));
                mx1 = fmaxf(mx1, fmaxf(sfr[nt][2], sfr[nt][3]));
            }
            mx0 = fmaxf(mx0, __shfl_xor_sync(0xffffffffu, mx0, 1));
            mx0 = fmaxf(mx0, __shfl_xor_sync(0xffffffffu, mx0, 2));
            mx1 = fmaxf(mx1, __shfl_xor_sync(0xffffffffu, mx1, 1));
            mx1 = fmaxf(mx1, __shfl_xor_sync(0xffffffffu, mx1, 2));

            const float mn0 = fmaxf(m0, mx0);
            const float mn1 = fmaxf(m1, mx1);
            const float a0 = ex2((m0 - mn0) * L2E);
            const float a1 = ex2((m1 - mn1) * L2E);
            m0 = mn0; m1 = mn1;

            float ls0 = 0.f, ls1 = 0.f;
#pragma unroll
            for (int nt = 0; nt < 8; nt++) {
                sfr[nt][0] = ex2((sfr[nt][0] - m0) * L2E);
                sfr[nt][1] = ex2((sfr[nt][1] - m0) * L2E);
                sfr[nt][2] = ex2((sfr[nt][2] - m1) * L2E);
                sfr[nt][3] = ex2((sfr[nt][3] - m1) * L2E);
                ls0 += sfr[nt][0] + sfr[nt][1];
                ls1 += sfr[nt][2] + sfr[nt][3];
            }
            ls0 += __shfl_xor_sync(0xffffffffu, ls0, 1);
            ls0 += __shfl_xor_sync(0xffffffffu, ls0, 2);
            ls1 += __shfl_xor_sync(0xffffffffu, ls1, 1);
            ls1 += __shfl_xor_sync(0xffffffffu, ls1, 2);
            l0 = l0 * a0 + ls0;
            l1 = l1 * a1 + ls1;

#pragma unroll
            for (int nt = 0; nt < 8; nt++) {
                o[nt][0] *= a0; o[nt][1] *= a0;
                o[nt][2] *= a1; o[nt][3] *= a1;
            }

            // ---- remap P (C-frag layout -> A-frag layout) via quad shuffles ----
            uint32_t pf[8][4];
            const int s0 = tig >> 1;
            const int s1 = s0 + 2;
            const bool odd = (tig & 1);
#pragma unroll
            for (int kk = 0; kk < 8; kk++) {
                float c0 = sfr[kk][0], c1 = sfr[kk][1];
                float c2 = sfr[kk][2], c3 = sfr[kk][3];
                float e00 = __shfl_sync(0xffffffffu, c0, s0, 4);
                float e01 = __shfl_sync(0xffffffffu, c1, s0, 4);
                float e10 = __shfl_sync(0xffffffffu, c0, s1, 4);
                float e11 = __shfl_sync(0xffffffffu, c1, s1, 4);
                float f00 = __shfl_sync(0xffffffffu, c2, s0, 4);
                float f01 = __shfl_sync(0xffffffffu, c3, s0, 4);
                float f10 = __shfl_sync(0xffffffffu, c2, s1, 4);
                float f11 = __shfl_sync(0xffffffffu, c3, s1, 4);
                pf[kk][0] = f2tf32(odd ? e01 : e00);
                pf[kk][1] = f2tf32(odd ? f01 : f00);
                pf[kk][2] = f2tf32(odd ? e11 : e10);
                pf[kk][3] = f2tf32(odd ? f11 : f10);
            }

            // ---- O += P @ V ----
#pragma unroll
            for (int nt = 0; nt < 8; nt++) {
#pragma unroll
                for (int kk = 0; kk < 8; kk++) {
                    uint32_t bf[2];
                    bf[0] = Vs[(kk * 8 + tig) * KST + nt * 8 + gid];
                    bf[1] = Vs[(kk * 8 + tig + 4) * KST + nt * 8 + gid];
                    mma_tf32(o[nt], pf[kk], bf, o[nt]);
                }
            }
        }
    }

    // ---- epilogue: O /= l, write to g_att [B,S,D] ----
    const float inv0 = 1.f / l0;
    const float inv1 = 1.f / l1;
    const int r0 = wrow0 + gid;
    float* ob0 = g_att + ((size_t)(b * S_ + r0)) * D_ + h * HD_;
    float* ob1 = g_att + ((size_t)(b * S_ + r0 + 8)) * D_ + h * HD_;
#pragma unroll
    for (int nt = 0; nt < 8; nt++) {
        float2 w0 = make_float2(o[nt][0] * inv0, o[nt][1] * inv0);
        float2 w1 = make_float2(o[nt][2] * inv1, o[nt][3] * inv1);
        *(float2*)&ob0[nt * 8 + 2 * tig] = w0;
        *(float2*)&ob1[nt * 8 + 2 * tig] = w1;
    }
}

// ---------------------------------------------------------------------------
extern "C" void kernel_launch(void* const* d_in, const int* in_sizes, int n_in,
                              void* d_out, int out_size)
{
    const float* hidden   = (const float*)d_in[0];  // [2,2048,768]
    const float* c_attn_w = (const float*)d_in[1];  // [768,2304]
    const float* c_attn_b = (const float*)d_in[2];  // [2304]
    const float* c_proj_w = (const float*)d_in[3];  // [768,768]
    const float* c_proj_b = (const float*)d_in[4];  // [768]
    float* out = (float*)d_out;

    // Phase 1: QKV GEMM + head split
    {
        dim3 grid(N_QKV / 128, M_ / 128);   // (18, 32)
        mma_gemm<0><<<grid, 256>>>(hidden, c_attn_w, c_attn_b, nullptr,
                                   D_, N_QKV);
    }
    // Phase 2: causal flash attention (tf32 mma)
    {
        dim3 grid(S_ / 64, H_, B_);         // (32, 12, 2)
        attn_mma<<<grid, 128>>>();
    }
    // Phase 3: output projection
    {
        float* g_att_ptr = nullptr;
        cudaGetSymbolAddress((void**)&g_att_ptr, g_att);
        dim3 grid(D_ / 128, M_ / 128);      // (6, 32)
        mma_gemm<1><<<grid, 256>>>(g_att_ptr, c_proj_w, c_proj_b, out,
                                   D_, D_);
    }
}

// round 3
// speedup vs baseline: 3.8974x; 1.0395x over previous
#include <cuda_runtime.h>
#include <cuda_bf16.h>
#include <cstdint>

// GPT2 attention block on tf32 tensor cores with ldmatrix fragment feeds.
// B=2, S=2048, D=768, H=12, hd=64

#define B_ 2
#define S_ 2048
#define D_ 768
#define H_ 12
#define HD_ 64
#define M_ (B_ * S_)        // 4096
#define N_QKV (3 * D_)      // 2304
#define MASKED_BIAS (-10000.0f)
#define L2E 1.4426950408889634f

// Scratch (no cudaMalloc allowed)
__device__ __align__(128) float g_q[B_ * H_ * S_ * HD_];
__device__ __align__(128) float g_k[B_ * H_ * S_ * HD_];
__device__ __align__(128) float g_v[B_ * H_ * S_ * HD_];
__device__ __align__(128) float g_att[M_ * D_];

// ---------------------------------------------------------------------------
__device__ __forceinline__ uint32_t f2tf32(float x) {
    uint32_t r;
    asm("cvt.rna.tf32.f32 %0, %1;" : "=r"(r) : "f"(x));
    return r;
}
__device__ __forceinline__ float ex2(float x) {
    float y;
    asm("ex2.approx.f32 %0, %1;" : "=f"(y) : "f"(x));
    return y;
}
__device__ __forceinline__ void mma_tf32(float d[4], const uint32_t a[4],
                                         const uint32_t b0, const uint32_t b1,
                                         const float c[4]) {
    asm volatile(
        "mma.sync.aligned.m16n8k8.row.col.f32.tf32.tf32.f32 "
        "{%0,%1,%2,%3}, {%4,%5,%6,%7}, {%8,%9}, {%10,%11,%12,%13};\n"
        : "=f"(d[0]), "=f"(d[1]), "=f"(d[2]), "=f"(d[3])
        : "r"(a[0]), "r"(a[1]), "r"(a[2]), "r"(a[3]),
          "r"(b0), "r"(b1),
          "f"(c[0]), "f"(c[1]), "f"(c[2]), "f"(c[3]));
}
__device__ __forceinline__ void ldsm4(uint32_t r[4], uint32_t addr) {
    asm volatile("ldmatrix.sync.aligned.m8n8.x4.shared.b16 {%0,%1,%2,%3}, [%4];"
        : "=r"(r[0]), "=r"(r[1]), "=r"(r[2]), "=r"(r[3]) : "r"(addr));
}
__device__ __forceinline__ uint4 cvt4(float4 v) {
    uint4 t;
    t.x = f2tf32(v.x); t.y = f2tf32(v.y);
    t.z = f2tf32(v.z); t.w = f2tf32(v.w);
    return t;
}

// ---------------------------------------------------------------------------
// TF32 GEMM: 128x128x32, 256 threads (8 warps of 64x32), 2-stage smem,
// ldmatrix fragment loads, XOR-swizzled layouts.
// MODE 0: C = X @ Wqkv + b -> scatter into g_q/g_k/g_v [B,H,S,hd]
// MODE 1: C = g_att @ Wproj + b -> Cout row-major
// smem: As[2][128*32] then Bs[2][128*32] (uint32), dynamic, 64KB total.
// As: [row m][k], 32 floats/row, 16B-group g stored at g^(row&7).
// Bs: [row n][k], same swizzle (transposed on store).
// ---------------------------------------------------------------------------
template <int MODE>
__global__ __launch_bounds__(256) void mma_gemm(
    const float* __restrict__ A,   // [M, K] row-major
    const float* __restrict__ Bm,  // [K, N] row-major
    const float* __restrict__ bias,
    float* __restrict__ Cout,
    int K, int N)
{
    constexpr int BM = 128, BN = 128, BK = 32;
    constexpr int STAGE_A = BM * BK;           // uint32 elems
    constexpr int STAGE_B = BN * BK;

    extern __shared__ uint32_t smem[];
    uint32_t* As = smem;                        // [2][STAGE_A]
    uint32_t* Bs = smem + 2 * STAGE_A;          // [2][STAGE_B]

    const int tid = threadIdx.x;
    const int lane = tid & 31;
    const int wid = tid >> 5;
    const int wm = wid & 1;
    const int wn = wid >> 1;
    const int gid = lane >> 2;
    const int tig = lane & 3;
    const int l7 = lane & 7;
    const int bm = blockIdx.y, bn = blockIdx.x;

    // ---- A gmem/smem mapping ----
    const int ar = tid >> 3, ac4 = tid & 7;
    const float* aldg = A + (size_t)(bm * BM + ar) * K + ac4 * 4;
    const int asw = (ac4 ^ (ar & 7)) * 4;       // uint32 offset within row

    // ---- B gmem/smem mapping (transpose on store) ----
    const int bnn = tid & 127, bkh = tid >> 7;
    const float* bldg = Bm + (size_t)(bkh * 16) * N + bn * BN + bnn;

    float acc[4][4][4];
#pragma unroll
    for (int i = 0; i < 4; i++)
#pragma unroll
        for (int j = 0; j < 4; j++)
#pragma unroll
            for (int r = 0; r < 4; r++) acc[i][j][r] = 0.f;

    float4 pa[4];
    float pb[16];

    // ldmatrix base addresses (bytes into shared)
    const uint32_t baseA = (uint32_t)__cvta_generic_to_shared(As);
    const uint32_t baseB = (uint32_t)__cvta_generic_to_shared(Bs);
    // A frag: row = wm*64 + mt*16 + l7 + ((lane>>3)&1)*8 ; kg = kk*2 + (lane>>4)
    const uint32_t arowb = (uint32_t)((wm * 64 + l7 + ((lane >> 3) & 1) * 8) * BK * 4);
    uint32_t aswz[4];
#pragma unroll
    for (int kk = 0; kk < 4; kk++)
        aswz[kk] = (uint32_t)((((kk * 2 + (lane >> 4)) ^ l7)) * 16);
    // B frag: row = wn*32 + nt*8 + l7 ; kg = kkp*4 + (lane>>3)
    const uint32_t browb = (uint32_t)((wn * 32 + l7) * BK * 4);
    uint32_t bswz[2];
#pragma unroll
    for (int kkp = 0; kkp < 2; kkp++)
        bswz[kkp] = (uint32_t)((((kkp * 4 + (lane >> 3)) ^ l7)) * 16);

#define LDGA(kt)                                                              \
    {                                                                         \
        _Pragma("unroll")                                                     \
        for (int u = 0; u < 4; u++)                                           \
            pa[u] = *(const float4*)(aldg + (size_t)u * 32 * K + (kt) * BK);  \
    }
#define LDGB(kt)                                                              \
    {                                                                         \
        const float* p = bldg + (size_t)(kt) * BK * N;                        \
        _Pragma("unroll")                                                     \
        for (int j = 0; j < 4; j++)                                           \
            _Pragma("unroll")                                                 \
            for (int e = 0; e < 4; e++)                                       \
                pb[j * 4 + e] = p[(size_t)(j * 4 + e) * N];                   \
    }
#define STS(st)                                                               \
    {                                                                         \
        uint32_t* as = As + (st) * STAGE_A;                                   \
        uint32_t* bs = Bs + (st) * STAGE_B;                                   \
        _Pragma("unroll")                                                     \
        for (int u = 0; u < 4; u++) {                                         \
            uint4 t = cvt4(pa[u]);                                            \
            *(uint4*)&as[(ar + u * 32) * BK + asw] = t;                       \
        }                                                                     \
        _Pragma("unroll")                                                     \
        for (int j = 0; j < 4; j++) {                                         \
            uint4 t;                                                          \
            t.x = f2tf32(pb[j * 4 + 0]); t.y = f2tf32(pb[j * 4 + 1]);         \
            t.z = f2tf32(pb[j * 4 + 2]); t.w = f2tf32(pb[j * 4 + 3]);         \
            *(uint4*)&bs[bnn * BK + (((bkh * 4 + j) ^ (bnn & 7)) * 4)] = t;   \
        }                                                                     \
    }

    LDGA(0); LDGB(0);
    STS(0);
    __syncthreads();

    const int ksteps = K / BK;
    for (int kt = 0; kt < ksteps; kt++) {
        if (kt + 1 < ksteps) { LDGA(kt + 1); LDGB(kt + 1); }

        const uint32_t stA = baseA + (uint32_t)((kt & 1) * STAGE_A * 4);
        const uint32_t stB = baseB + (uint32_t)((kt & 1) * STAGE_B * 4);
#pragma unroll
        for (int kkp = 0; kkp < 2; kkp++) {
            uint32_t bf[4][4];   // [nt] = {kk_lo, kk_hi, kk1_lo, kk1_hi}
#pragma unroll
            for (int nt = 0; nt < 4; nt++)
                ldsm4(bf[nt], stB + browb + nt * (8 * BK * 4) + bswz[kkp]);
#pragma unroll
            for (int s = 0; s < 2; s++) {
                const int kk = kkp * 2 + s;
                uint32_t af[4][4];
#pragma unroll
                for (int mt = 0; mt < 4; mt++)
                    ldsm4(af[mt], stA + arowb + mt * (16 * BK * 4) + aswz[kk]);
#pragma unroll
                for (int mt = 0; mt < 4; mt++)
#pragma unroll
                    for (int nt = 0; nt < 4; nt++)
                        mma_tf32(acc[mt][nt], af[mt],
                                 bf[nt][s * 2], bf[nt][s * 2 + 1], acc[mt][nt]);
            }
        }

        if (kt + 1 < ksteps) {
            STS((kt + 1) & 1);
            __syncthreads();
        }
    }

    // epilogue
#pragma unroll
    for (int mt = 0; mt < 4; mt++) {
#pragma unroll
        for (int nt = 0; nt < 4; nt++) {
#pragma unroll
            for (int r = 0; r < 4; r++) {
                int m = bm * BM + wm * 64 + mt * 16 + gid + ((r >= 2) ? 8 : 0);
                int n = bn * BN + wn * 32 + nt * 8 + 2 * tig + (r & 1);
                float val = acc[mt][nt][r] + bias[n];
                if (MODE == 0) {
                    const int which = n / D_;
                    const int d2 = n - which * D_;
                    const int h = d2 >> 6;
                    const int hi = d2 & 63;
                    const int b = m >> 11;
                    const int s = m & 2047;
                    float* dst = (which == 0) ? g_q : (which == 1) ? g_k : g_v;
                    dst[(((size_t)(b * H_ + h) * S_) + s) * HD_ + hi] = val;
                } else {
                    Cout[(size_t)m * N + n] = val;
                }
            }
        }
    }
#undef LDGA
#undef LDGB
#undef STS
}

// ---------------------------------------------------------------------------
// Flash attention, tf32 mma + ldmatrix. 128 threads (4 warps), Br=64, Bc=64.
// Ks[key][d]  (d-minor, swizzled)  -> QK B-frags via ldmatrix
// Vt[d][key]  (key-minor, swizzled, transposed on load) -> PV B-frags via ldmatrix
// ---------------------------------------------------------------------------
__global__ __launch_bounds__(128) void attn_mma()
{
    const int qtile = gridDim.x - 1 - blockIdx.x;  // heavy tiles first
    const int h = blockIdx.y;
    const int b = blockIdx.z;
    const int tid = threadIdx.x;
    const int lane = tid & 31;
    const int wid = tid >> 5;
    const int gid = lane >> 2;
    const int tig = lane & 3;
    const int l7 = lane & 7;

    const int q0 = qtile * 64;
    const int wrow0 = q0 + wid * 16;

    const float* qb = g_q + ((size_t)(b * H_ + h) * S_) * HD_;
    const float* kb = g_k + ((size_t)(b * H_ + h) * S_) * HD_;
    const float* vb = g_v + ((size_t)(b * H_ + h) * S_) * HD_;

    // preload Q fragments (scaled by 1/sqrt(64))
    uint32_t qf[8][4];
#pragma unroll
    for (int kk = 0; kk < 8; kk++) {
        int r0 = wrow0 + gid;
        int c = kk * 8 + tig;
        qf[kk][0] = f2tf32(qb[(size_t)r0 * HD_ + c] * 0.125f);
        qf[kk][1] = f2tf32(qb[(size_t)(r0 + 8) * HD_ + c] * 0.125f);
        qf[kk][2] = f2tf32(qb[(size_t)r0 * HD_ + c + 4] * 0.125f);
        qf[kk][3] = f2tf32(qb[(size_t)(r0 + 8) * HD_ + c + 4] * 0.125f);
    }

    float o[8][4];
#pragma unroll
    for (int nt = 0; nt < 8; nt++)
#pragma unroll
        for (int r = 0; r < 4; r++) o[nt][r] = 0.f;

    float m0 = -1e30f, m1 = -1e30f, l0 = 0.f, l1 = 0.f;

    __shared__ uint32_t Ks[64 * 64];
    __shared__ uint32_t Vt[64 * 64];
    const uint32_t baseK = (uint32_t)__cvta_generic_to_shared(Ks);
    const uint32_t baseV = (uint32_t)__cvta_generic_to_shared(Vt);

    uint32_t swz[4];
#pragma unroll
    for (int kkp = 0; kkp < 4; kkp++)
        swz[kkp] = (uint32_t)((((kkp * 4 + (lane >> 3)) ^ l7)) * 16);
    const uint32_t rowb = (uint32_t)(l7 * 256);   // l7 * 64 floats * 4B

    const int vd = tid & 63, vkh = tid >> 6;

    for (int t = 0; t <= qtile; t++) {
        const int k0 = t * 64;
        __syncthreads();
        // K tile: [key][d], float4 loads, swizzled STS.128
#pragma unroll
        for (int u = 0; u < 8; u++) {
            int idx = tid + u * 128;
            int row = idx >> 4, dg = idx & 15;
            float4 kv = *(const float4*)(kb + (size_t)(k0 + row) * HD_ + dg * 4);
            *(uint4*)&Ks[row * 64 + ((dg ^ (row & 7)) * 4)] = cvt4(kv);
        }
        // V tile transposed: Vt[d][key]
#pragma unroll
        for (int j = 0; j < 8; j++) {
            int key = vkh * 32 + j * 4;
            const float* vp = vb + (size_t)(k0 + key) * HD_ + vd;
            float4 vv;
            vv.x = vp[0]; vv.y = vp[HD_]; vv.z = vp[2 * HD_]; vv.w = vp[3 * HD_];
            int kg = vkh * 8 + j;
            *(uint4*)&Vt[vd * 64 + ((kg ^ (vd & 7)) * 4)] = cvt4(vv);
        }
        __syncthreads();

        const bool active = (k0 <= wrow0 + 15);
        if (active) {
            // ---- S = Q @ K^T ----
            float sfr[8][4];
#pragma unroll
            for (int nt = 0; nt < 8; nt++) {
#pragma unroll
                for (int r = 0; r < 4; r++) sfr[nt][r] = 0.f;
#pragma unroll
                for (int kkp = 0; kkp < 4; kkp++) {
                    uint32_t bf[4];
                    ldsm4(bf, baseK + rowb + nt * 2048 + swz[kkp]);
                    mma_tf32(sfr[nt], qf[kkp * 2], bf[0], bf[1], sfr[nt]);
                    mma_tf32(sfr[nt], qf[kkp * 2 + 1], bf[2], bf[3], sfr[nt]);
                }
            }

            const int r0 = wrow0 + gid;
            const int r1 = r0 + 8;
            if (k0 + 63 > wrow0) {
#pragma unroll
                for (int nt = 0; nt < 8; nt++) {
                    int c = k0 + nt * 8 + 2 * tig;
                    if (c > r0) sfr[nt][0] = MASKED_BIAS;
                    if (c + 1 > r0) sfr[nt][1] = MASKED_BIAS;
                    if (c > r1) sfr[nt][2] = MASKED_BIAS;
                    if (c + 1 > r1) sfr[nt][3] = MASKED_BIAS;
                }
            }

            // ---- online softmax ----
            float mx0 = -1e30f, mx1 = -1e30f;
#pragma unroll
            for (int nt = 0; nt < 8; nt++) {
                mx0 = fmaxf(mx0, fmaxf(sfr[nt][0], sfr[nt][1]));
                mx1 = fmaxf(mx1, fmaxf(sfr[nt][2], sfr[nt][3]));
            }
            mx0 = fmaxf(mx0, __shfl_xor_sync(0xffffffffu, mx0, 1));
            mx0 = fmaxf(mx0, __shfl_xor_sync(0xffffffffu, mx0, 2));
            mx1 = fmaxf(mx1, __shfl_xor_sync(0xffffffffu, mx1, 1));
            mx1 = fmaxf(mx1, __shfl_xor_sync(0xffffffffu, mx1, 2));

            const float mn0 = fmaxf(m0, mx0);
            const float mn1 = fmaxf(m1, mx1);
            const float a0 = ex2((m0 - mn0) * L2E);
            const float a1 = ex2((m1 - mn1) * L2E);
            m0 = mn0; m1 = mn1;

            float ls0 = 0.f, ls1 = 0.f;
#pragma unroll
            for (int nt = 0; nt < 8; nt++) {
                sfr[nt][0] = ex2((sfr[nt][0] - m0) * L2E);
                sfr[nt][1] = ex2((sfr[nt][1] - m0) * L2E);
                sfr[nt][2] = ex2((sfr[nt][2] - m1) * L2E);
                sfr[nt][3] = ex2((sfr[nt][3] - m1) * L2E);
                ls0 += sfr[nt][0] + sfr[nt][1];
                ls1 += sfr[nt][2] + sfr[nt][3];
            }
            ls0 += __shfl_xor_sync(0xffffffffu, ls0, 1);
            ls0 += __shfl_xor_sync(0xffffffffu, ls0, 2);
            ls1 += __shfl_xor_sync(0xffffffffu, ls1, 1);
            ls1 += __shfl_xor_sync(0xffffffffu, ls1, 2);
            l0 = l0 * a0 + ls0;
            l1 = l1 * a1 + ls1;

#pragma unroll
            for (int nt = 0; nt < 8; nt++) {
                o[nt][0] *= a0; o[nt][1] *= a0;
                o[nt][2] *= a1; o[nt][3] *= a1;
            }

            // ---- remap P C-frag -> A-frag via quad shuffles ----
            uint32_t pf[8][4];
            const int s0 = tig >> 1;
            const int s1 = s0 + 2;
            const bool odd = (tig & 1);
#pragma unroll
            for (int kk = 0; kk < 8; kk++) {
                float c0 = sfr[kk][0], c1 = sfr[kk][1];
                float c2 = sfr[kk][2], c3 = sfr[kk][3];
                float e00 = __shfl_sync(0xffffffffu, c0, s0, 4);
                float e01 = __shfl_sync(0xffffffffu, c1, s0, 4);
                float e10 = __shfl_sync(0xffffffffu, c0, s1, 4);
                float e11 = __shfl_sync(0xffffffffu, c1, s1, 4);
                float f00 = __shfl_sync(0xffffffffu, c2, s0, 4);
                float f01 = __shfl_sync(0xffffffffu, c3, s0, 4);
                float f10 = __shfl_sync(0xffffffffu, c2, s1, 4);
                float f11 = __shfl_sync(0xffffffffu, c3, s1, 4);
                pf[kk][0] = f2tf32(odd ? e01 : e00);
                pf[kk][1] = f2tf32(odd ? f01 : f00);
                pf[kk][2] = f2tf32(odd ? e11 : e10);
                pf[kk][3] = f2tf32(odd ? f11 : f10);
            }

            // ---- O += P @ V ----
#pragma unroll
            for (int nt = 0; nt < 8; nt++) {
#pragma unroll
                for (int kkp = 0; kkp < 4; kkp++) {
                    uint32_t bf[4];
                    ldsm4(bf, baseV + rowb + nt * 2048 + swz[kkp]);
                    mma_tf32(o[nt], pf[kkp * 2], bf[0], bf[1], o[nt]);
                    mma_tf32(o[nt], pf[kkp * 2 + 1], bf[2], bf[3], o[nt]);
                }
            }
        }
    }

    // ---- epilogue ----
    const float inv0 = 1.f / l0;
    const float inv1 = 1.f / l1;
    const int r0 = wrow0 + gid;
    float* ob0 = g_att + ((size_t)(b * S_ + r0)) * D_ + h * HD_;
    float* ob1 = g_att + ((size_t)(b * S_ + r0 + 8)) * D_ + h * HD_;
#pragma unroll
    for (int nt = 0; nt < 8; nt++) {
        float2 w0 = make_float2(o[nt][0] * inv0, o[nt][1] * inv0);
        float2 w1 = make_float2(o[nt][2] * inv1, o[nt][3] * inv1);
        *(float2*)&ob0[nt * 8 + 2 * tig] = w0;
        *(float2*)&ob1[nt * 8 + 2 * tig] = w1;
    }
}

// ---------------------------------------------------------------------------
extern "C" void kernel_launch(void* const* d_in, const int* in_sizes, int n_in,
                              void* d_out, int out_size)
{
    const float* hidden   = (const float*)d_in[0];
    const float* c_attn_w = (const float*)d_in[1];
    const float* c_attn_b = (const float*)d_in[2];
    const float* c_proj_w = (const float*)d_in[3];
    const float* c_proj_b = (const float*)d_in[4];
    float* out = (float*)d_out;

    constexpr int SMEM_GEMM = 2 * (128 * 32 + 128 * 32) * 4;  // 64KB

    static bool attr_set = false;
    if (!attr_set) {
        cudaFuncSetAttribute(mma_gemm<0>,
            cudaFuncAttributeMaxDynamicSharedMemorySize, SMEM_GEMM);
        cudaFuncSetAttribute(mma_gemm<1>,
            cudaFuncAttributeMaxDynamicSharedMemorySize, SMEM_GEMM);
        attr_set = true;
    }

    // Phase 1: QKV GEMM + head split
    {
        dim3 grid(N_QKV / 128, M_ / 128);
        mma_gemm<0><<<grid, 256, SMEM_GEMM>>>(hidden, c_attn_w, c_attn_b,
                                              nullptr, D_, N_QKV);
    }
    // Phase 2: causal flash attention
    {
        dim3 grid(S_ / 64, H_, B_);
        attn_mma<<<grid, 128>>>();
    }
    // Phase 3: output projection
    {
        float* g_att_ptr = nullptr;
        cudaGetSymbolAddress((void**)&g_att_ptr, g_att);
        dim3 grid(D_ / 128, M_ / 128);
        mma_gemm<1><<<grid, 256, SMEM_GEMM>>>(g_att_ptr, c_proj_w, c_proj_b,
                                              out, D_, D_);
    }
}

// round 4
// speedup vs baseline: 5.6152x; 1.4408x over previous
#include <cuda_runtime.h>
#include <cuda_bf16.h>
#include <cstdint>

// GPT2 attention block, tf32 mma.sync + cp.async pipelines, pre-converted operands.
// B=2, S=2048, D=768, H=12, hd=64

#define B_ 2
#define S_ 2048
#define D_ 768
#define H_ 12
#define HD_ 64
#define M_ (B_ * S_)        // 4096
#define N_QKV (3 * D_)      // 2304
#define MASKED_BIAS (-10000.0f)
#define L2E 1.4426950408889634f

// Scratch (no cudaMalloc allowed)
__device__ __align__(128) float g_q[B_ * H_ * S_ * HD_];   // [b,h,s,d] tf32, pre-scaled 1/8
__device__ __align__(128) float g_k[B_ * H_ * S_ * HD_];   // [b,h,s,d] tf32
__device__ __align__(128) float g_v[B_ * H_ * S_ * HD_];   // [b,h,d,s] tf32 (TRANSPOSED)
__device__ __align__(128) float g_att[M_ * D_];            // tf32-rounded
__device__ __align__(128) float g_x[M_ * D_];              // hidden, tf32
__device__ __align__(128) float g_wqkv_t[N_QKV * D_];      // [n][k] tf32
__device__ __align__(128) float g_wp_t[D_ * D_];           // [n][k] tf32

// ---------------------------------------------------------------------------
__device__ __forceinline__ uint32_t f2tf32(float x) {
    uint32_t r;
    asm("cvt.rna.tf32.f32 %0, %1;" : "=r"(r) : "f"(x));
    return r;
}
__device__ __forceinline__ float ex2(float x) {
    float y;
    asm("ex2.approx.f32 %0, %1;" : "=f"(y) : "f"(x));
    return y;
}
__device__ __forceinline__ void mma_tf32(float d[4], const uint32_t a[4],
                                         const uint32_t b0, const uint32_t b1,
                                         const float c[4]) {
    asm volatile(
        "mma.sync.aligned.m16n8k8.row.col.f32.tf32.tf32.f32 "
        "{%0,%1,%2,%3}, {%4,%5,%6,%7}, {%8,%9}, {%10,%11,%12,%13};\n"
        : "=f"(d[0]), "=f"(d[1]), "=f"(d[2]), "=f"(d[3])
        : "r"(a[0]), "r"(a[1]), "r"(a[2]), "r"(a[3]),
          "r"(b0), "r"(b1),
          "f"(c[0]), "f"(c[1]), "f"(c[2]), "f"(c[3]));
}
__device__ __forceinline__ void ldsm4(uint32_t r[4], uint32_t addr) {
    asm volatile("ldmatrix.sync.aligned.m8n8.x4.shared.b16 {%0,%1,%2,%3}, [%4];"
        : "=r"(r[0]), "=r"(r[1]), "=r"(r[2]), "=r"(r[3]) : "r"(addr));
}
__device__ __forceinline__ void cp16(uint32_t dst, const void* src) {
    asm volatile("cp.async.cg.shared.global [%0], [%1], 16;\n"
                 :: "r"(dst), "l"(src));
}
__device__ __forceinline__ void cp_commit() {
    asm volatile("cp.async.commit_group;\n");
}
template <int N>
__device__ __forceinline__ void cp_wait() {
    asm volatile("cp.async.wait_group %0;\n" :: "n"(N));
}

// ---------------------------------------------------------------------------
// Pre-pass kernels
// ---------------------------------------------------------------------------
__global__ void cvt_copy(const float* __restrict__ src, float* __restrict__ dst,
                         int n4) {
    int i = blockIdx.x * blockDim.x + threadIdx.x;
    if (i < n4) {
        float4 v = ((const float4*)src)[i];
        uint4 t;
        t.x = f2tf32(v.x); t.y = f2tf32(v.y);
        t.z = f2tf32(v.z); t.w = f2tf32(v.w);
        ((uint4*)dst)[i] = t;
    }
}

// src [R][C] row-major -> dst [C][R], tf32-rounded.  block 32x8, grid (C/32, R/32)
__global__ void transpose_cvt(const float* __restrict__ src,
                              float* __restrict__ dst, int R, int C) {
    __shared__ float tile[32][33];
    const int c0 = blockIdx.x * 32, r0 = blockIdx.y * 32;
    const int x = threadIdx.x, y = threadIdx.y;
#pragma unroll
    for (int j = 0; j < 32; j += 8)
        tile[y + j][x] = src[(size_t)(r0 + y + j) * C + c0 + x];
    __syncthreads();
#pragma unroll
    for (int j = 0; j < 32; j += 8)
        ((uint32_t*)dst)[(size_t)(c0 + y + j) * R + r0 + x] =
            f2tf32(tile[x][y + j]);
}

// ---------------------------------------------------------------------------
// TF32 GEMM: 128x128x32, 256 threads (8 warps 64x32), cp.async 3-stage,
// both operands k-minor tf32 in gmem, ldmatrix frags, XOR swizzle.
// MODE 0: scatter into g_q (scaled), g_k, g_v(transposed).  MODE 1: Cout.
// ---------------------------------------------------------------------------
template <int MODE>
__global__ __launch_bounds__(256, 2) void mma_gemm(
    const float* __restrict__ A,   // [M][K] tf32
    const float* __restrict__ Bt,  // [N][K] tf32
    const float* __restrict__ bias,
    float* __restrict__ Cout,
    int K, int N)
{
    constexpr int BM = 128, BN = 128, BK = 32;
    constexpr int STAGE_U32 = (BM + BN) * BK;   // 8192 (32KB)

    extern __shared__ uint32_t smem[];
    const uint32_t sbase = (uint32_t)__cvta_generic_to_shared(smem);

    const int tid = threadIdx.x;
    const int lane = tid & 31;
    const int wid = tid >> 5;
    const int wm = wid & 1, wn = wid >> 1;
    const int gid = lane >> 2, tig = lane & 3, l7 = lane & 7;
    const int bm = blockIdx.y, bn = blockIdx.x;

    // ldgsts mapping: 32 rows x 8 groups per pass; u adds 32 rows
    const int row_ = tid >> 3, g_ = tid & 7;
    const float* asrc = A + (size_t)(bm * BM + row_) * K + g_ * 4;
    const float* bsrc = Bt + (size_t)(bn * BN + row_) * K + g_ * 4;
    const uint32_t dofs = (uint32_t)((row_ * BK + ((g_ ^ (row_ & 7)) * 4)) * 4);

    auto issue = [&](int s, int kt) {
        const uint32_t sb = sbase + (uint32_t)(s * STAGE_U32 * 4);
        const float* ap = asrc + kt * BK;
        const float* bp = bsrc + kt * BK;
        const uint32_t ad = sb + dofs;
        const uint32_t bd = ad + (uint32_t)(BM * BK * 4);
#pragma unroll
        for (int u = 0; u < 4; u++) {
            cp16(ad + u * (32 * BK * 4), ap + (size_t)u * 32 * K);
            cp16(bd + u * (32 * BK * 4), bp + (size_t)u * 32 * K);
        }
    };

    // fragment addresses
    const uint32_t arowb = (uint32_t)((wm * 64 + l7 + ((lane >> 3) & 1) * 8) * BK * 4);
    uint32_t aswz[4];
#pragma unroll
    for (int kk = 0; kk < 4; kk++)
        aswz[kk] = (uint32_t)((((kk * 2 + (lane >> 4)) ^ l7)) * 16);
    const uint32_t browb = (uint32_t)((wn * 32 + l7) * BK * 4) + (uint32_t)(BM * BK * 4);
    uint32_t bswz[2];
#pragma unroll
    for (int kkp = 0; kkp < 2; kkp++)
        bswz[kkp] = (uint32_t)((((kkp * 4 + (lane >> 3)) ^ l7)) * 16);

    float acc[4][4][4];
#pragma unroll
    for (int i = 0; i < 4; i++)
#pragma unroll
        for (int j = 0; j < 4; j++)
#pragma unroll
            for (int r = 0; r < 4; r++) acc[i][j][r] = 0.f;

    issue(0, 0); cp_commit();
    issue(1, 1); cp_commit();

    const int ksteps = K / BK;
    int st = 0;
    for (int kt = 0; kt < ksteps; kt++) {
        cp_wait<1>();
        __syncthreads();
        const uint32_t sb = sbase + (uint32_t)(st * STAGE_U32 * 4);
#pragma unroll
        for (int kkp = 0; kkp < 2; kkp++) {
            uint32_t bf[4][4];
#pragma unroll
            for (int nt = 0; nt < 4; nt++)
                ldsm4(bf[nt], sb + browb + nt * (8 * BK * 4) + bswz[kkp]);
#pragma unroll
            for (int s = 0; s < 2; s++) {
                const int kk = kkp * 2 + s;
                uint32_t af[4][4];
#pragma unroll
                for (int mt = 0; mt < 4; mt++)
                    ldsm4(af[mt], sb + arowb + mt * (16 * BK * 4) + aswz[kk]);
#pragma unroll
                for (int mt = 0; mt < 4; mt++)
#pragma unroll
                    for (int nt = 0; nt < 4; nt++)
                        mma_tf32(acc[mt][nt], af[mt],
                                 bf[nt][s * 2], bf[nt][s * 2 + 1], acc[mt][nt]);
            }
        }
        if (kt + 2 < ksteps) {
            int s2 = st + 2; if (s2 >= 3) s2 -= 3;
            issue(s2, kt + 2);
        }
        cp_commit();
        if (++st == 3) st = 0;
    }

    // epilogue
#pragma unroll
    for (int mt = 0; mt < 4; mt++) {
#pragma unroll
        for (int nt = 0; nt < 4; nt++) {
#pragma unroll
            for (int r = 0; r < 4; r++) {
                int m = bm * BM + wm * 64 + mt * 16 + gid + ((r >= 2) ? 8 : 0);
                int n = bn * BN + wn * 32 + nt * 8 + 2 * tig + (r & 1);
                float val = acc[mt][nt][r] + bias[n];
                if (MODE == 0) {
                    const int which = n / D_;
                    const int d2 = n - which * D_;
                    const int h = d2 >> 6;
                    const int hi = d2 & 63;
                    const int b = m >> 11;
                    const int s = m & 2047;
                    if (which == 0) {
                        g_q[(((size_t)(b * H_ + h) * S_) + s) * HD_ + hi] =
                            __uint_as_float(f2tf32(val * 0.125f));
                    } else if (which == 1) {
                        g_k[(((size_t)(b * H_ + h) * S_) + s) * HD_ + hi] =
                            __uint_as_float(f2tf32(val));
                    } else {
                        g_v[((size_t)(b * H_ + h) * HD_ + hi) * S_ + s] =
                            __uint_as_float(f2tf32(val));
                    }
                } else {
                    Cout[(size_t)m * N + n] = val;
                }
            }
        }
    }
}

// ---------------------------------------------------------------------------
// Flash attention, tf32 mma + ldmatrix + cp.async double buffer.
// 128 threads (4 warps), Br=64, Bc=64. Inputs pre-rounded tf32, V transposed.
// ---------------------------------------------------------------------------
__global__ __launch_bounds__(128, 3) void attn_mma()
{
    const int qtile = gridDim.x - 1 - blockIdx.x;
    const int h = blockIdx.y;
    const int b = blockIdx.z;
    const int tid = threadIdx.x;
    const int lane = tid & 31;
    const int wid = tid >> 5;
    const int gid = lane >> 2, tig = lane & 3, l7 = lane & 7;

    const int q0 = qtile * 64;
    const int wrow0 = q0 + wid * 16;

    const uint32_t* qu = (const uint32_t*)(g_q + ((size_t)(b * H_ + h) * S_) * HD_);
    const float* kb = g_k + ((size_t)(b * H_ + h) * S_) * HD_;
    const float* vtb = g_v + ((size_t)(b * H_ + h) * HD_) * S_;

    // Q fragments, direct global (already tf32 bits, pre-scaled)
    uint32_t qf[8][4];
#pragma unroll
    for (int kk = 0; kk < 8; kk++) {
        const int r0 = wrow0 + gid;
        const int c = kk * 8 + tig;
        qf[kk][0] = qu[(size_t)r0 * HD_ + c];
        qf[kk][1] = qu[(size_t)(r0 + 8) * HD_ + c];
        qf[kk][2] = qu[(size_t)r0 * HD_ + c + 4];
        qf[kk][3] = qu[(size_t)(r0 + 8) * HD_ + c + 4];
    }

    float o[8][4];
#pragma unroll
    for (int nt = 0; nt < 8; nt++)
#pragma unroll
        for (int r = 0; r < 4; r++) o[nt][r] = 0.f;
    float m0 = -1e30f, m1 = -1e30f, l0 = 0.f, l1 = 0.f;

    extern __shared__ uint32_t asmem[];   // [2][8192]: K 16KB + Vt 16KB per stage
    const uint32_t sbase = (uint32_t)__cvta_generic_to_shared(asmem);

    const int row_ = tid >> 4, g_ = tid & 15;   // u adds 8 rows
    const uint32_t dofs = (uint32_t)((row_ * 64 + ((g_ ^ (row_ & 7)) * 4)) * 4);

    auto issueT = [&](int s, int t) {
        const int k0 = t * 64;
        const uint32_t kd = sbase + (uint32_t)(s * 32768) + dofs;
        const uint32_t vd = kd + 16384;
        const float* kp = kb + (size_t)(k0 + row_) * HD_ + g_ * 4;
        const float* vp = vtb + (size_t)row_ * S_ + k0 + g_ * 4;
#pragma unroll
        for (int u = 0; u < 8; u++) {
            cp16(kd + u * (8 * 64 * 4), kp + (size_t)u * 8 * HD_);
            cp16(vd + u * (8 * 64 * 4), vp + (size_t)u * 8 * S_);
        }
    };

    uint32_t swz[4];
#pragma unroll
    for (int kkp = 0; kkp < 4; kkp++)
        swz[kkp] = (uint32_t)((((kkp * 4 + (lane >> 3)) ^ l7)) * 16);
    const uint32_t rowb = (uint32_t)(l7 * 256);

    issueT(0, 0); cp_commit();

    for (int t = 0; t <= qtile; t++) {
        if (t < qtile) issueT((t + 1) & 1, t + 1);
        cp_commit();
        cp_wait<1>();
        __syncthreads();

        const uint32_t baseK = sbase + (uint32_t)((t & 1) * 32768);
        const uint32_t baseV = baseK + 16384;
        const int k0 = t * 64;

        const bool active = (k0 <= wrow0 + 15);
        if (active) {
            // ---- S = Q @ K^T ----
            float sfr[8][4];
#pragma unroll
            for (int nt = 0; nt < 8; nt++) {
#pragma unroll
                for (int r = 0; r < 4; r++) sfr[nt][r] = 0.f;
#pragma unroll
                for (int kkp = 0; kkp < 4; kkp++) {
                    uint32_t bf[4];
                    ldsm4(bf, baseK + rowb + nt * 2048 + swz[kkp]);
                    mma_tf32(sfr[nt], qf[kkp * 2], bf[0], bf[1], sfr[nt]);
                    mma_tf32(sfr[nt], qf[kkp * 2 + 1], bf[2], bf[3], sfr[nt]);
                }
            }

            const int r0 = wrow0 + gid;
            const int r1 = r0 + 8;
            if (k0 + 63 > wrow0) {
#pragma unroll
                for (int nt = 0; nt < 8; nt++) {
                    int c = k0 + nt * 8 + 2 * tig;
                    if (c > r0) sfr[nt][0] = MASKED_BIAS;
                    if (c + 1 > r0) sfr[nt][1] = MASKED_BIAS;
                    if (c > r1) sfr[nt][2] = MASKED_BIAS;
                    if (c + 1 > r1) sfr[nt][3] = MASKED_BIAS;
                }
            }

            // ---- online softmax ----
            float mx0 = -1e30f, mx1 = -1e30f;
#pragma unroll
            for (int nt = 0; nt < 8; nt++) {
                mx0 = fmaxf(mx0, fmaxf(sfr[nt][0], sfr[nt][1]));
                mx1 = fmaxf(mx1, fmaxf(sfr[nt][2], sfr[nt][3]));
            }
            mx0 = fmaxf(mx0, __shfl_xor_sync(0xffffffffu, mx0, 1));
            mx0 = fmaxf(mx0, __shfl_xor_sync(0xffffffffu, mx0, 2));
            mx1 = fmaxf(mx1, __shfl_xor_sync(0xffffffffu, mx1, 1));
            mx1 = fmaxf(mx1, __shfl_xor_sync(0xffffffffu, mx1, 2));

            const float mn0 = fmaxf(m0, mx0);
            const float mn1 = fmaxf(m1, mx1);
            const float a0 = ex2((m0 - mn0) * L2E);
            const float a1 = ex2((m1 - mn1) * L2E);
            m0 = mn0; m1 = mn1;

            float ls0 = 0.f, ls1 = 0.f;
#pragma unroll
            for (int nt = 0; nt < 8; nt++) {
                sfr[nt][0] = ex2((sfr[nt][0] - m0) * L2E);
                sfr[nt][1] = ex2((sfr[nt][1] - m0) * L2E);
                sfr[nt][2] = ex2((sfr[nt][2] - m1) * L2E);
                sfr[nt][3] = ex2((sfr[nt][3] - m1) * L2E);
                ls0 += sfr[nt][0] + sfr[nt][1];
                ls1 += sfr[nt][2] + sfr[nt][3];
            }
            ls0 += __shfl_xor_sync(0xffffffffu, ls0, 1);
            ls0 += __shfl_xor_sync(0xffffffffu, ls0, 2);
            ls1 += __shfl_xor_sync(0xffffffffu, ls1, 1);
            ls1 += __shfl_xor_sync(0xffffffffu, ls1, 2);
            l0 = l0 * a0 + ls0;
            l1 = l1 * a1 + ls1;

#pragma unroll
            for (int nt = 0; nt < 8; nt++) {
                o[nt][0] *= a0; o[nt][1] *= a0;
                o[nt][2] *= a1; o[nt][3] *= a1;
            }

            // ---- remap P C-frag -> A-frag via quad shuffles ----
            uint32_t pf[8][4];
            const int s0 = tig >> 1;
            const int s1 = s0 + 2;
            const bool odd = (tig & 1);
#pragma unroll
            for (int kk = 0; kk < 8; kk++) {
                float c0 = sfr[kk][0], c1 = sfr[kk][1];
                float c2 = sfr[kk][2], c3 = sfr[kk][3];
                float e00 = __shfl_sync(0xffffffffu, c0, s0, 4);
                float e01 = __shfl_sync(0xffffffffu, c1, s0, 4);
                float e10 = __shfl_sync(0xffffffffu, c0, s1, 4);
                float e11 = __shfl_sync(0xffffffffu, c1, s1, 4);
                float f00 = __shfl_sync(0xffffffffu, c2, s0, 4);
                float f01 = __shfl_sync(0xffffffffu, c3, s0, 4);
                float f10 = __shfl_sync(0xffffffffu, c2, s1, 4);
                float f11 = __shfl_sync(0xffffffffu, c3, s1, 4);
                pf[kk][0] = f2tf32(odd ? e01 : e00);
                pf[kk][1] = f2tf32(odd ? f01 : f00);
                pf[kk][2] = f2tf32(odd ? e11 : e10);
                pf[kk][3] = f2tf32(odd ? f11 : f10);
            }

            // ---- O += P @ V ----
#pragma unroll
            for (int nt = 0; nt < 8; nt++) {
#pragma unroll
                for (int kkp = 0; kkp < 4; kkp++) {
                    uint32_t bf[4];
                    ldsm4(bf, baseV + rowb + nt * 2048 + swz[kkp]);
                    mma_tf32(o[nt], pf[kkp * 2], bf[0], bf[1], o[nt]);
                    mma_tf32(o[nt], pf[kkp * 2 + 1], bf[2], bf[3], o[nt]);
                }
            }
        }
        __syncthreads();
    }

    // ---- epilogue: tf32-rounded store for proj GEMM ----
    const float inv0 = 1.f / l0;
    const float inv1 = 1.f / l1;
    const int r0 = wrow0 + gid;
    uint32_t* ob0 = (uint32_t*)(g_att + ((size_t)(b * S_ + r0)) * D_ + h * HD_);
    uint32_t* ob1 = (uint32_t*)(g_att + ((size_t)(b * S_ + r0 + 8)) * D_ + h * HD_);
#pragma unroll
    for (int nt = 0; nt < 8; nt++) {
        uint2 w0, w1;
        w0.x = f2tf32(o[nt][0] * inv0); w0.y = f2tf32(o[nt][1] * inv0);
        w1.x = f2tf32(o[nt][2] * inv1); w1.y = f2tf32(o[nt][3] * inv1);
        *(uint2*)&ob0[nt * 8 + 2 * tig] = w0;
        *(uint2*)&ob1[nt * 8 + 2 * tig] = w1;
    }
}

// ---------------------------------------------------------------------------
extern "C" void kernel_launch(void* const* d_in, const int* in_sizes, int n_in,
                              void* d_out, int out_size)
{
    const float* hidden   = (const float*)d_in[0];
    const float* c_attn_w = (const float*)d_in[1];
    const float* c_attn_b = (const float*)d_in[2];
    const float* c_proj_w = (const float*)d_in[3];
    const float* c_proj_b = (const float*)d_in[4];
    float* out = (float*)d_out;

    constexpr int SMEM_GEMM = 3 * (128 + 128) * 32 * 4;  // 96KB
    constexpr int SMEM_ATTN = 2 * (64 * 64 + 64 * 64) * 4;  // 64KB

    static bool attr_set = false;
    if (!attr_set) {
        cudaFuncSetAttribute(mma_gemm<0>,
            cudaFuncAttributeMaxDynamicSharedMemorySize, SMEM_GEMM);
        cudaFuncSetAttribute(mma_gemm<1>,
            cudaFuncAttributeMaxDynamicSharedMemorySize, SMEM_GEMM);
        cudaFuncSetAttribute(attn_mma,
            cudaFuncAttributeMaxDynamicSharedMemorySize, SMEM_ATTN);
        attr_set = true;
    }

    float *px, *pwq, *pwp, *patt;
    cudaGetSymbolAddress((void**)&px, g_x);
    cudaGetSymbolAddress((void**)&pwq, g_wqkv_t);
    cudaGetSymbolAddress((void**)&pwp, g_wp_t);
    cudaGetSymbolAddress((void**)&patt, g_att);

    // Pre-pass: tf32-convert hidden, transpose+convert weights
    {
        int n4 = M_ * D_ / 4;
        cvt_copy<<<(n4 + 255) / 256, 256>>>(hidden, px, n4);
        dim3 blk(32, 8);
        transpose_cvt<<<dim3(N_QKV / 32, D_ / 32), blk>>>(c_attn_w, pwq, D_, N_QKV);
        transpose_cvt<<<dim3(D_ / 32, D_ / 32), blk>>>(c_proj_w, pwp, D_, D_);
    }
    // Phase 1: QKV GEMM + head split (+ q scaling, v transpose, tf32 rounding)
    {
        dim3 grid(N_QKV / 128, M_ / 128);
        mma_gemm<0><<<grid, 256, SMEM_GEMM>>>(px, pwq, c_attn_b, nullptr,
                                              D_, N_QKV);
    }
    // Phase 2: causal flash attention
    {
        dim3 grid(S_ / 64, H_, B_);
        attn_mma<<<grid, 128, SMEM_ATTN>>>();
    }
    // Phase 3: output projection
    {
        dim3 grid(D_ / 128, M_ / 128);
        mma_gemm<1><<<grid, 256, SMEM_GEMM>>>(patt, pwp, c_proj_b, out,
                                              D_, D_);
    }
}